// round 3
// baseline (speedup 1.0000x reference)
#include <cuda_runtime.h>
#include <cstdint>

// Problem constants (fixed shapes per reference)
#define HH 128
#define NNODES 100000

// Scratch: per-node projected tables, 256 floats each.
//   T[n][0:128]   = z[n] @ W1a
//   T[n][128:256] = z[n] @ W1b + b1
__device__ float g_Tp[(size_t)NNODES * 256];
__device__ float g_To[(size_t)NNODES * 256];
// Rearranged weight: Wc[k][j] = (j<128) ? w1[k][j] : w1[k+128][j-128],  k in [0,128)
__device__ float g_Wc[128 * 256];

// ---------------------------------------------------------------------------
// Pack w1 [256,128] row-major into Wc [128,256]
// ---------------------------------------------------------------------------
__global__ void pack_w_kernel(const float* __restrict__ w1) {
    int k = blockIdx.x;      // 0..127
    int j = threadIdx.x;     // 0..255
    float v = (j < 128) ? w1[k * 128 + j] : w1[(k + 128) * 128 + (j - 128)];
    g_Wc[k * 256 + j] = v;
}

// ---------------------------------------------------------------------------
// SGEMM: C[M,256] = Z[M,128] @ Wc[128,256], +b1 on columns >=128.
// Block tile 128x128, BK=16, 256 threads, 8x8 per-thread microtile.
// gridDim.z selects (z_pnode -> g_Tp) or (z_onode -> g_To).
// ---------------------------------------------------------------------------
#define BM 128
#define BN 128
#define BK 16

__global__ void __launch_bounds__(256, 2) sgemm_kernel(
    const float* __restrict__ Zp, const float* __restrict__ Zo,
    const float* __restrict__ b1, int M)
{
    const float* __restrict__ Z = (blockIdx.z == 0) ? Zp : Zo;
    float* __restrict__ C = (blockIdx.z == 0) ? g_Tp : g_To;

    __shared__ float As[BK][BM];      // transposed A tile
    __shared__ float Bs[BK][BN];

    const int tid = threadIdx.x;
    const int m0 = blockIdx.x * BM;
    const int n0 = blockIdx.y * BN;
    const int ty = tid >> 4;          // 0..15
    const int tx = tid & 15;          // 0..15

    float acc[8][8];
#pragma unroll
    for (int i = 0; i < 8; i++)
#pragma unroll
        for (int j = 0; j < 8; j++) acc[i][j] = 0.f;

    for (int kt = 0; kt < 128; kt += BK) {
        // Load A tile: 128 rows x 16 cols = 512 float4, 2 per thread
#pragma unroll
        for (int i = 0; i < 2; i++) {
            int li = tid + i * 256;       // 0..511
            int row = li >> 2;            // 0..127
            int c4 = li & 3;              // float4 index within 16 cols
            float4 v = make_float4(0.f, 0.f, 0.f, 0.f);
            int gr = m0 + row;
            if (gr < M)
                v = *(const float4*)(Z + (size_t)gr * 128 + kt + c4 * 4);
            As[c4 * 4 + 0][row] = v.x;
            As[c4 * 4 + 1][row] = v.y;
            As[c4 * 4 + 2][row] = v.z;
            As[c4 * 4 + 3][row] = v.w;
        }
        // Load B tile: 16 rows x 128 cols = 512 float4, 2 per thread
#pragma unroll
        for (int i = 0; i < 2; i++) {
            int li = tid + i * 256;
            int r = li >> 5;              // 0..15
            int c4 = li & 31;             // 0..31
            float4 v = *(const float4*)(g_Wc + (size_t)(kt + r) * 256 + n0 + c4 * 4);
            *(float4*)(&Bs[r][c4 * 4]) = v;
        }
        __syncthreads();

#pragma unroll
        for (int kk = 0; kk < BK; kk++) {
            float af[8], bf[8];
#pragma unroll
            for (int i = 0; i < 8; i++) af[i] = As[kk][ty * 8 + i];
#pragma unroll
            for (int j = 0; j < 8; j++) bf[j] = Bs[kk][tx * 8 + j];
#pragma unroll
            for (int i = 0; i < 8; i++)
#pragma unroll
                for (int j = 0; j < 8; j++)
                    acc[i][j] = fmaf(af[i], bf[j], acc[i][j]);
        }
        __syncthreads();
    }

    // Epilogue: add b1 to the second 128 columns (blockIdx.y==1), vector stores.
    float bb[8];
#pragma unroll
    for (int j = 0; j < 8; j++)
        bb[j] = (blockIdx.y == 1) ? b1[tx * 8 + j] : 0.f;

#pragma unroll
    for (int i = 0; i < 8; i++) {
        int gr = m0 + ty * 8 + i;
        if (gr < M) {
            float* crow = C + (size_t)gr * 256 + n0 + tx * 8;
            float4 v0, v1;
            v0.x = acc[i][0] + bb[0]; v0.y = acc[i][1] + bb[1];
            v0.z = acc[i][2] + bb[2]; v0.w = acc[i][3] + bb[3];
            v1.x = acc[i][4] + bb[4]; v1.y = acc[i][5] + bb[5];
            v1.z = acc[i][6] + bb[6]; v1.w = acc[i][7] + bb[7];
            *(float4*)(crow + 0) = v0;
            *(float4*)(crow + 4) = v1;
        }
    }
}

// ---------------------------------------------------------------------------
// Edge kernel: one warp per edge. Gather the two half-rows (128 floats each),
// u = a + b (b1 pre-folded), out = relu(u) . w2 + b2.
// Edge types:
//   0 (ptnp):  a = Tp[src][0:128], b = To[dst][128:256]
//   1 (nptp):  a = To[src][0:128], b = Tp[dst][128:256]
//   2 (nptnp): a = To[src][0:128], b = To[dst][128:256]
// ---------------------------------------------------------------------------
__global__ void __launch_bounds__(256) edge_kernel(
    const int* __restrict__ idx0, const int* __restrict__ idx1,
    const int* __restrict__ idx2,
    const float* __restrict__ w2, const float* __restrict__ b2,
    float* __restrict__ out, int E)
{
    int warp = (blockIdx.x * blockDim.x + threadIdx.x) >> 5;
    int lane = threadIdx.x & 31;
    if (warp >= 3 * E) return;

    int type = warp / E;
    int e = warp - type * E;

    const int* __restrict__ idx = (type == 0) ? idx0 : (type == 1) ? idx1 : idx2;
    int src = idx[e];
    int dst = idx[e + E];

    const float* Ta;
    const float* Tb;
    if (type == 0)      { Ta = g_Tp; Tb = g_To; }
    else if (type == 1) { Ta = g_To; Tb = g_Tp; }
    else                { Ta = g_To; Tb = g_To; }

    float4 va = *((const float4*)(Ta + (size_t)src * 256) + lane);
    float4 vb = *((const float4*)(Tb + (size_t)dst * 256 + 128) + lane);
    float4 w  = ((const float4*)w2)[lane];

    float s = fmaxf(va.x + vb.x, 0.f) * w.x
            + fmaxf(va.y + vb.y, 0.f) * w.y
            + fmaxf(va.z + vb.z, 0.f) * w.z
            + fmaxf(va.w + vb.w, 0.f) * w.w;

#pragma unroll
    for (int off = 16; off > 0; off >>= 1)
        s += __shfl_xor_sync(0xFFFFFFFFu, s, off);

    if (lane == 0) out[warp] = s + b2[0];
}

// ---------------------------------------------------------------------------
// kernel_launch
// Inputs (metadata order):
//  0: z_pnode  f32 [100000,128]
//  1: z_onode  f32 [100000,128]
//  2: ptnp_edge_label_index  i32 [2,500000]
//  3: nptp_edge_label_index  i32 [2,500000]
//  4: nptnp_edge_label_index i32 [2,500000]
//  5: w1 f32 [256,128]
//  6: b1 f32 [128]
//  7: w2 f32 [128,1]
//  8: b2 f32 [1]
// Output: f32 [1500000]
// ---------------------------------------------------------------------------
extern "C" void kernel_launch(void* const* d_in, const int* in_sizes, int n_in,
                              void* d_out, int out_size)
{
    const float* z_pnode = (const float*)d_in[0];
    const float* z_onode = (const float*)d_in[1];
    const int*   idx0    = (const int*)d_in[2];
    const int*   idx1    = (const int*)d_in[3];
    const int*   idx2    = (const int*)d_in[4];
    const float* w1      = (const float*)d_in[5];
    const float* b1      = (const float*)d_in[6];
    const float* w2      = (const float*)d_in[7];
    const float* b2      = (const float*)d_in[8];
    float*       out     = (float*)d_out;

    int M = in_sizes[0] / HH;       // 100000
    int E = in_sizes[2] / 2;        // 500000

    // 1. Rearrange weights
    pack_w_kernel<<<128, 256>>>(w1);

    // 2. Precompute node tables (both matrices via gridDim.z)
    dim3 ggrid((M + BM - 1) / BM, 2, 2);
    sgemm_kernel<<<ggrid, 256>>>(z_pnode, z_onode, b1, M);

    // 3. Edge phase: one warp per edge, 8 edges per 256-thread block
    int total_warps = 3 * E;
    int blocks = (total_warps + 7) / 8;
    edge_kernel<<<blocks, 256>>>(idx0, idx1, idx2, w2, b2, out, E);
}

// round 4
// speedup vs baseline: 1.4955x; 1.4955x over previous
#include <cuda_runtime.h>
#include <cstdint>

#define HH 128
#define NNODES 100000

// Per-node projected tables: T[n][0:128] = z@W1a, T[n][128:256] = z@W1b + b1
__device__ float g_Tp[(size_t)NNODES * 256];
__device__ float g_To[(size_t)NNODES * 256];
// Wc[k][j] = (j<128) ? w1[k][j] : w1[k+128][j-128]
__device__ float g_Wc[128 * 256];

// ---------------------------------------------------------------------------
__global__ void pack_w_kernel(const float* __restrict__ w1) {
    int k = blockIdx.x;
    int j = threadIdx.x;
    float v = (j < 128) ? w1[k * 128 + j] : w1[(k + 128) * 128 + (j - 128)];
    g_Wc[k * 256 + j] = v;
}

// ---------------------------------------------------------------------------
// TF32 tensor-core GEMM: C[M,256] = Z[M,128] @ Wc[128,256] (+b1 on cols>=128)
// Block tile 128x128, BK=32, 256 threads (8 warps, 4Mx2N), warp tile 32x64.
// ---------------------------------------------------------------------------
#define BM 128
#define BN 128
#define BK 32
#define AS_STRIDE 36    // %32==4 -> a-frag reads conflict-free
#define BS_STRIDE 136   // %32==8 -> b-frag reads conflict-free

__device__ __forceinline__ uint32_t f2tf32(float x) {
    uint32_t r;
    asm("cvt.rna.tf32.f32 %0, %1;" : "=r"(r) : "f"(x));
    return r;
}

__device__ __forceinline__ void mma_tf32(float* d, const uint32_t* a, const uint32_t* b) {
    asm volatile(
        "mma.sync.aligned.m16n8k8.row.col.f32.tf32.tf32.f32 "
        "{%0,%1,%2,%3}, {%4,%5,%6,%7}, {%8,%9}, {%0,%1,%2,%3};"
        : "+f"(d[0]), "+f"(d[1]), "+f"(d[2]), "+f"(d[3])
        : "r"(a[0]), "r"(a[1]), "r"(a[2]), "r"(a[3]), "r"(b[0]), "r"(b[1]));
}

__global__ void __launch_bounds__(256, 2) gemm_tf32_kernel(
    const float* __restrict__ Zp, const float* __restrict__ Zo,
    const float* __restrict__ b1, int M)
{
    const float* __restrict__ Z = (blockIdx.z == 0) ? Zp : Zo;
    float* __restrict__ C = (blockIdx.z == 0) ? g_Tp : g_To;

    __shared__ uint32_t As[BM * AS_STRIDE];   // [row][k], tf32 bits
    __shared__ uint32_t Bs[BK * BS_STRIDE];   // [k][n],   tf32 bits

    const int tid = threadIdx.x;
    const int lane = tid & 31;
    const int wid = tid >> 5;
    const int warpM = wid & 3;          // 0..3 -> 32-row slab
    const int warpN = wid >> 2;         // 0..1 -> 64-col slab
    const int g  = lane >> 2;           // groupID 0..7
    const int tg = lane & 3;            // thread-in-group 0..3

    const int m0 = blockIdx.x * BM;
    const int n0 = blockIdx.y * BN;

    float acc[2][8][4];
#pragma unroll
    for (int mt = 0; mt < 2; mt++)
#pragma unroll
        for (int nt = 0; nt < 8; nt++)
#pragma unroll
            for (int q = 0; q < 4; q++) acc[mt][nt][q] = 0.f;

    for (int kt = 0; kt < 128; kt += BK) {
        // --- fill A tile: 128 rows x 32 k = 1024 float4, 4/thread ---
#pragma unroll
        for (int i = 0; i < 4; i++) {
            int idx = tid + i * 256;         // 0..1023
            int row = idx >> 3;              // 0..127
            int c4  = idx & 7;               // k-float4 0..7
            float4 v = make_float4(0.f, 0.f, 0.f, 0.f);
            int gr = m0 + row;
            if (gr < M)
                v = *(const float4*)(Z + (size_t)gr * 128 + kt + c4 * 4);
            uint32_t* p = &As[row * AS_STRIDE + c4 * 4];
            // word index = 36*row + 4*c4 : multiple of 4 -> 16B aligned
            uint4 t;
            t.x = f2tf32(v.x); t.y = f2tf32(v.y);
            t.z = f2tf32(v.z); t.w = f2tf32(v.w);
            *(uint4*)p = t;
        }
        // --- fill B tile: 32 k x 128 n = 1024 float4, 4/thread ---
#pragma unroll
        for (int i = 0; i < 4; i++) {
            int idx = tid + i * 256;
            int r  = idx >> 5;               // 0..31
            int c4 = idx & 31;               // 0..31
            float4 v = *(const float4*)(g_Wc + (size_t)(kt + r) * 256 + n0 + c4 * 4);
            uint4 t;
            t.x = f2tf32(v.x); t.y = f2tf32(v.y);
            t.z = f2tf32(v.z); t.w = f2tf32(v.w);
            *(uint4*)(&Bs[r * BS_STRIDE + c4 * 4]) = t;
        }
        __syncthreads();

#pragma unroll
        for (int ks = 0; ks < 4; ks++) {
            const int k0 = ks * 8;
            uint32_t a[2][4];
#pragma unroll
            for (int mt = 0; mt < 2; mt++) {
                int rbase = warpM * 32 + mt * 16;
                a[mt][0] = As[(rbase + g)     * AS_STRIDE + k0 + tg];
                a[mt][1] = As[(rbase + g + 8) * AS_STRIDE + k0 + tg];
                a[mt][2] = As[(rbase + g)     * AS_STRIDE + k0 + tg + 4];
                a[mt][3] = As[(rbase + g + 8) * AS_STRIDE + k0 + tg + 4];
            }
#pragma unroll
            for (int nt = 0; nt < 8; nt++) {
                int nb = warpN * 64 + nt * 8 + g;
                uint32_t b[2];
                b[0] = Bs[(k0 + tg)     * BS_STRIDE + nb];
                b[1] = Bs[(k0 + tg + 4) * BS_STRIDE + nb];
                mma_tf32(acc[0][nt], a[0], b);
                mma_tf32(acc[1][nt], a[1], b);
            }
        }
        __syncthreads();
    }

    // --- epilogue: +b1 on global cols >=128, float2 stores ---
#pragma unroll
    for (int nt = 0; nt < 8; nt++) {
        int coll = warpN * 64 + nt * 8 + 2 * tg;   // local col in [0,128)
        float bx = 0.f, by = 0.f;
        if (blockIdx.y == 1) { bx = b1[coll]; by = b1[coll + 1]; }
#pragma unroll
        for (int mt = 0; mt < 2; mt++) {
            int row0 = m0 + warpM * 32 + mt * 16 + g;
            int row1 = row0 + 8;
            int col = n0 + coll;
            if (row0 < M) {
                float2 v; v.x = acc[mt][nt][0] + bx; v.y = acc[mt][nt][1] + by;
                *(float2*)(C + (size_t)row0 * 256 + col) = v;
            }
            if (row1 < M) {
                float2 v; v.x = acc[mt][nt][2] + bx; v.y = acc[mt][nt][3] + by;
                *(float2*)(C + (size_t)row1 * 256 + col) = v;
            }
        }
    }
}

// ---------------------------------------------------------------------------
// Edge kernel: one warp per edge.  u = Ta[src][0:128] + Tb[dst][128:256],
// out = relu(u) . w2 + b2.
// ---------------------------------------------------------------------------
__global__ void __launch_bounds__(256) edge_kernel(
    const int* __restrict__ idx0, const int* __restrict__ idx1,
    const int* __restrict__ idx2,
    const float* __restrict__ w2, const float* __restrict__ b2,
    float* __restrict__ out, int E)
{
    int warp = (blockIdx.x * blockDim.x + threadIdx.x) >> 5;
    int lane = threadIdx.x & 31;
    if (warp >= 3 * E) return;

    int type = warp / E;
    int e = warp - type * E;

    const int* __restrict__ idx = (type == 0) ? idx0 : (type == 1) ? idx1 : idx2;
    int src = idx[e];
    int dst = idx[e + E];

    const float* Ta;
    const float* Tb;
    if (type == 0)      { Ta = g_Tp; Tb = g_To; }
    else if (type == 1) { Ta = g_To; Tb = g_Tp; }
    else                { Ta = g_To; Tb = g_To; }

    float4 va = *((const float4*)(Ta + (size_t)src * 256) + lane);
    float4 vb = *((const float4*)(Tb + (size_t)dst * 256 + 128) + lane);
    float4 w  = ((const float4*)w2)[lane];

    float s = fmaxf(va.x + vb.x, 0.f) * w.x
            + fmaxf(va.y + vb.y, 0.f) * w.y
            + fmaxf(va.z + vb.z, 0.f) * w.z
            + fmaxf(va.w + vb.w, 0.f) * w.w;

#pragma unroll
    for (int off = 16; off > 0; off >>= 1)
        s += __shfl_xor_sync(0xFFFFFFFFu, s, off);

    if (lane == 0) out[warp] = s + b2[0];
}

// ---------------------------------------------------------------------------
extern "C" void kernel_launch(void* const* d_in, const int* in_sizes, int n_in,
                              void* d_out, int out_size)
{
    const float* z_pnode = (const float*)d_in[0];
    const float* z_onode = (const float*)d_in[1];
    const int*   idx0    = (const int*)d_in[2];
    const int*   idx1    = (const int*)d_in[3];
    const int*   idx2    = (const int*)d_in[4];
    const float* w1      = (const float*)d_in[5];
    const float* b1      = (const float*)d_in[6];
    const float* w2      = (const float*)d_in[7];
    const float* b2      = (const float*)d_in[8];
    float*       out     = (float*)d_out;

    int M = in_sizes[0] / HH;       // 100000
    int E = in_sizes[2] / 2;        // 500000

    pack_w_kernel<<<128, 256>>>(w1);

    dim3 ggrid((M + BM - 1) / BM, 2, 2);
    gemm_tf32_kernel<<<ggrid, 256>>>(z_pnode, z_onode, b1, M);

    int total_warps = 3 * E;
    int blocks = (total_warps + 7) / 8;
    edge_kernel<<<blocks, 256>>>(idx0, idx1, idx2, w2, b2, out, E);
}

// round 5
// speedup vs baseline: 1.5446x; 1.0329x over previous
#include <cuda_runtime.h>
#include <cuda_fp16.h>
#include <cstdint>

#define HH 128
#define NNODES 100000

// Per-node projected tables in fp16: T[n][0:128] = z@W1a, T[n][128:256] = z@W1b + b1
__device__ __half g_Tp[(size_t)NNODES * 256];
__device__ __half g_To[(size_t)NNODES * 256];

// ---------------------------------------------------------------------------
// TF32 tensor-core GEMM: C[M,256] = Z[M,128] @ Wc[128,256] (+b1 on cols>=128),
// output stored as fp16. Wc is addressed directly from w1 (block-uniform remap).
// Block tile 128x128, BK=32, 256 threads (8 warps, 4Mx2N), warp tile 32x64.
// ---------------------------------------------------------------------------
#define BM 128
#define BN 128
#define BK 32
#define AS_STRIDE 36    // %32==4 -> a-frag reads conflict-free
#define BS_STRIDE 136   // %32==8 -> b-frag reads conflict-free

__device__ __forceinline__ uint32_t f2tf32(float x) {
    uint32_t r;
    asm("cvt.rna.tf32.f32 %0, %1;" : "=r"(r) : "f"(x));
    return r;
}

__device__ __forceinline__ void mma_tf32(float* d, const uint32_t* a, const uint32_t* b) {
    asm volatile(
        "mma.sync.aligned.m16n8k8.row.col.f32.tf32.tf32.f32 "
        "{%0,%1,%2,%3}, {%4,%5,%6,%7}, {%8,%9}, {%0,%1,%2,%3};"
        : "+f"(d[0]), "+f"(d[1]), "+f"(d[2]), "+f"(d[3])
        : "r"(a[0]), "r"(a[1]), "r"(a[2]), "r"(a[3]), "r"(b[0]), "r"(b[1]));
}

__global__ void __launch_bounds__(256, 2) gemm_tf32_kernel(
    const float* __restrict__ Zp, const float* __restrict__ Zo,
    const float* __restrict__ w1, const float* __restrict__ b1, int M)
{
    const float* __restrict__ Z = (blockIdx.z == 0) ? Zp : Zo;
    __half* __restrict__ C = (blockIdx.z == 0) ? g_Tp : g_To;

    __shared__ uint32_t As[BM * AS_STRIDE];   // [row][k], tf32 bits
    __shared__ uint32_t Bs[BK * BS_STRIDE];   // [k][n],   tf32 bits

    const int tid = threadIdx.x;
    const int lane = tid & 31;
    const int wid = tid >> 5;
    const int warpM = wid & 3;          // 0..3 -> 32-row slab
    const int warpN = wid >> 2;         // 0..1 -> 64-col slab
    const int g  = lane >> 2;           // groupID 0..7
    const int tg = lane & 3;            // thread-in-group 0..3

    const int m0 = blockIdx.x * BM;
    // Wc[k][n0+c] = w1[(k + (blockIdx.y?128:0))*128 + c]
    const float* __restrict__ Wsrc = w1 + (blockIdx.y ? (size_t)128 * 128 : 0);

    float acc[2][8][4];
#pragma unroll
    for (int mt = 0; mt < 2; mt++)
#pragma unroll
        for (int nt = 0; nt < 8; nt++)
#pragma unroll
            for (int q = 0; q < 4; q++) acc[mt][nt][q] = 0.f;

    for (int kt = 0; kt < 128; kt += BK) {
        // --- fill A tile: 128 rows x 32 k = 1024 float4, 4/thread ---
#pragma unroll
        for (int i = 0; i < 4; i++) {
            int idx = tid + i * 256;         // 0..1023
            int row = idx >> 3;              // 0..127
            int c4  = idx & 7;               // k-float4 0..7
            float4 v = make_float4(0.f, 0.f, 0.f, 0.f);
            int gr = m0 + row;
            if (gr < M)
                v = *(const float4*)(Z + (size_t)gr * 128 + kt + c4 * 4);
            uint4 t;
            t.x = f2tf32(v.x); t.y = f2tf32(v.y);
            t.z = f2tf32(v.z); t.w = f2tf32(v.w);
            *(uint4*)(&As[row * AS_STRIDE + c4 * 4]) = t;
        }
        // --- fill B tile: 32 k x 128 n = 1024 floats, read w1 directly ---
#pragma unroll
        for (int i = 0; i < 4; i++) {
            int idx = tid + i * 256;
            int r  = idx >> 5;               // k-row 0..31
            int c4 = idx & 31;               // float4 col 0..31
            float4 v = *(const float4*)(Wsrc + (size_t)(kt + r) * 128 + c4 * 4);
            uint4 t;
            t.x = f2tf32(v.x); t.y = f2tf32(v.y);
            t.z = f2tf32(v.z); t.w = f2tf32(v.w);
            *(uint4*)(&Bs[r * BS_STRIDE + c4 * 4]) = t;
        }
        __syncthreads();

#pragma unroll
        for (int ks = 0; ks < 4; ks++) {
            const int k0 = ks * 8;
            uint32_t a[2][4];
#pragma unroll
            for (int mt = 0; mt < 2; mt++) {
                int rbase = warpM * 32 + mt * 16;
                a[mt][0] = As[(rbase + g)     * AS_STRIDE + k0 + tg];
                a[mt][1] = As[(rbase + g + 8) * AS_STRIDE + k0 + tg];
                a[mt][2] = As[(rbase + g)     * AS_STRIDE + k0 + tg + 4];
                a[mt][3] = As[(rbase + g + 8) * AS_STRIDE + k0 + tg + 4];
            }
#pragma unroll
            for (int nt = 0; nt < 8; nt++) {
                int nb = warpN * 64 + nt * 8 + g;
                uint32_t b[2];
                b[0] = Bs[(k0 + tg)     * BS_STRIDE + nb];
                b[1] = Bs[(k0 + tg + 4) * BS_STRIDE + nb];
                mma_tf32(acc[0][nt], a[0], b);
                mma_tf32(acc[1][nt], a[1], b);
            }
        }
        __syncthreads();
    }

    // --- epilogue: +b1 on second half (blockIdx.y==1), fp16 stores ---
#pragma unroll
    for (int nt = 0; nt < 8; nt++) {
        int coll = warpN * 64 + nt * 8 + 2 * tg;   // local col in [0,128), even
        float bx = 0.f, by = 0.f;
        if (blockIdx.y == 1) { bx = b1[coll]; by = b1[coll + 1]; }
        int col = blockIdx.y * 128 + coll;         // global col in [0,256)
#pragma unroll
        for (int mt = 0; mt < 2; mt++) {
            int row0 = m0 + warpM * 32 + mt * 16 + g;
            int row1 = row0 + 8;
            if (row0 < M) {
                __half2 h = __floats2half2_rn(acc[mt][nt][0] + bx, acc[mt][nt][1] + by);
                *(__half2*)(C + (size_t)row0 * 256 + col) = h;
            }
            if (row1 < M) {
                __half2 h = __floats2half2_rn(acc[mt][nt][2] + bx, acc[mt][nt][3] + by);
                *(__half2*)(C + (size_t)row1 * 256 + col) = h;
            }
        }
    }
}

// ---------------------------------------------------------------------------
// Edge kernel: one warp per edge.  u = Ta[src][0:128] + Tb[dst][128:256] (fp16
// tables, fp32 math), out = relu(u) . w2 + b2.  Each lane: 4 consecutive cols.
// ---------------------------------------------------------------------------
__global__ void __launch_bounds__(256) edge_kernel(
    const int* __restrict__ idx0, const int* __restrict__ idx1,
    const int* __restrict__ idx2,
    const float* __restrict__ w2, const float* __restrict__ b2,
    float* __restrict__ out, int E)
{
    int warp = (blockIdx.x * blockDim.x + threadIdx.x) >> 5;
    int lane = threadIdx.x & 31;
    if (warp >= 3 * E) return;

    int type = warp / E;
    int e = warp - type * E;

    const int* __restrict__ idx = (type == 0) ? idx0 : (type == 1) ? idx1 : idx2;
    int src = idx[e];
    int dst = idx[e + E];

    const __half* Ta;
    const __half* Tb;
    if (type == 0)      { Ta = g_Tp; Tb = g_To; }
    else if (type == 1) { Ta = g_To; Tb = g_Tp; }
    else                { Ta = g_To; Tb = g_To; }

    // lane covers cols [4*lane, 4*lane+4): two half2 loads packed as uint2
    uint2 ua = *((const uint2*)(Ta + (size_t)src * 256) + lane);
    uint2 ub = *((const uint2*)(Tb + (size_t)dst * 256 + 128) + lane);
    float4 w = ((const float4*)w2)[lane];

    float2 a0 = __half22float2(*(const __half2*)&ua.x);
    float2 a1 = __half22float2(*(const __half2*)&ua.y);
    float2 b0 = __half22float2(*(const __half2*)&ub.x);
    float2 b1v = __half22float2(*(const __half2*)&ub.y);

    float s = fmaxf(a0.x + b0.x, 0.f) * w.x
            + fmaxf(a0.y + b0.y, 0.f) * w.y
            + fmaxf(a1.x + b1v.x, 0.f) * w.z
            + fmaxf(a1.y + b1v.y, 0.f) * w.w;

#pragma unroll
    for (int off = 16; off > 0; off >>= 1)
        s += __shfl_xor_sync(0xFFFFFFFFu, s, off);

    if (lane == 0) out[warp] = s + b2[0];
}

// ---------------------------------------------------------------------------
extern "C" void kernel_launch(void* const* d_in, const int* in_sizes, int n_in,
                              void* d_out, int out_size)
{
    const float* z_pnode = (const float*)d_in[0];
    const float* z_onode = (const float*)d_in[1];
    const int*   idx0    = (const int*)d_in[2];
    const int*   idx1    = (const int*)d_in[3];
    const int*   idx2    = (const int*)d_in[4];
    const float* w1      = (const float*)d_in[5];
    const float* b1      = (const float*)d_in[6];
    const float* w2      = (const float*)d_in[7];
    const float* b2      = (const float*)d_in[8];
    float*       out     = (float*)d_out;

    int M = in_sizes[0] / HH;       // 100000
    int E = in_sizes[2] / 2;        // 500000

    dim3 ggrid((M + BM - 1) / BM, 2, 2);
    gemm_tf32_kernel<<<ggrid, 256>>>(z_pnode, z_onode, w1, b1, M);

    int total_warps = 3 * E;
    int blocks = (total_warps + 7) / 8;
    edge_kernel<<<blocks, 256>>>(idx0, idx1, idx2, w2, b2, out, E);
}